// round 8
// baseline (speedup 1.0000x reference)
#include <cuda_runtime.h>
#include <cuda_bf16.h>

#define LGT      16
#define NROWS    4096
#define DCOLS    16000              // CLASSNUM * LGT
#define NWORKERS (152 * 8)          // GB300: 152 SMs, 8 CTAs/SM resident
#define VEC_PER_WARP 500            // (DCOLS/4)/8 float4 per warp chunk

__device__ float        g_acc  = 0.0f;
__device__ unsigned int g_cnt  = 0u;
__device__ unsigned int g_task = 0u;

__global__ __launch_bounds__(256, 8)
void rvsml_loss_kernel(const float* __restrict__ inputs,
                       const float* __restrict__ labels,
                       float* __restrict__ out) {
    const int tid  = threadIdx.x;
    const int wid  = tid >> 5;
    const int lane = tid & 31;

    __shared__ float    warp_sums[8];
    __shared__ unsigned next_sh[2];   // parity double-buffered ticket

    // Prologue: first ticket
    if (tid == 0) next_sh[0] = atomicAdd(&g_task, 1u);
    __syncthreads();
    unsigned row = next_sh[0];

    float total = 0.0f;   // per-thread running contribution
    int   k     = 0;      // iteration parity

    while (row < NROWS) {
        // Prefetch next ticket into the other parity slot; ATOMG latency
        // hides under the row stream. Safe: slot (k+1)&1 was last read
        // before the previous barrier.
        if (tid == 0) next_sh[(k + 1) & 1] = atomicAdd(&g_task, 1u);

        // ---- Labels (per-warp, broadcast loads; no block sync) ----
        const float* lab = labels + row * (LGT + 1);
        float lv = (lane <= LGT) ? __ldg(lab + lane) : 0.0f;
        const int   c = (int)__shfl_sync(0xFFFFFFFFu, lv, LGT);
        const float w = (lane < LGT) ? lv : 0.0f;
        float W = w;
        #pragma unroll
        for (int off = 16; off > 0; off >>= 1)
            W += __shfl_xor_sync(0xFFFFFFFFu, W, off);

        // ---- Stream this warp's 1/8 chunk of the row ----
        const float4* p = reinterpret_cast<const float4*>(inputs + (size_t)row * DCOLS)
                        + wid * VEC_PER_WARP;
        float sq = 0.0f;
        #pragma unroll 5
        for (int it = 0; it < 15; it++) {          // 15*32 = 480 vecs
            float4 v = p[lane + it * 32];
            sq = fmaf(v.x, v.x, sq);
            sq = fmaf(v.y, v.y, sq);
            sq = fmaf(v.z, v.z, sq);
            sq = fmaf(v.w, v.w, sq);
        }
        if (lane < VEC_PER_WARP - 480) {           // remainder: 20 vecs
            float4 v = p[480 + lane];
            sq = fmaf(v.x, v.x, sq);
            sq = fmaf(v.y, v.y, sq);
            sq = fmaf(v.z, v.z, sq);
            sq = fmaf(v.w, v.w, sq);
        }
        total = fmaf(W, sq, total);                // W_i * sq_chunk

        // ---- Gather term, once per row (warp 0) ----
        if (wid == 0 && lane < LGT) {
            const float g = __ldg(inputs + (size_t)row * DCOLS + c * LGT + lane);
            total = fmaf(w, 1.0f - 2.0f * g, total);
        }

        // ---- Single barrier per row: publish ticket ----
        __syncthreads();
        row = next_sh[(k + 1) & 1];
        k++;
    }

    // ---- One block reduce + one global atomic per CTA ----
    #pragma unroll
    for (int off = 16; off > 0; off >>= 1)
        total += __shfl_xor_sync(0xFFFFFFFFu, total, off);
    if (lane == 0) warp_sums[wid] = total;
    __syncthreads();

    if (tid < 32) {
        float v = (tid < 8) ? warp_sums[tid] : 0.0f;
        #pragma unroll
        for (int off = 4; off > 0; off >>= 1)
            v += __shfl_xor_sync(0xFFFFFFFFu, v, off);

        if (tid == 0) {
            atomicAdd(&g_acc, v);
            __threadfence();
            const unsigned done = atomicAdd(&g_cnt, 1u);
            if (done == NWORKERS - 1) {
                // All contributions visible (each CTA fenced before its
                // counter increment). Read + reset for the next graph replay.
                const float t = atomicExch(&g_acc, 0.0f);
                out[0] = t * (1.0f / (float)NROWS);
                g_cnt  = 0u;
                g_task = 0u;
                __threadfence();
            }
        }
    }
}

extern "C" void kernel_launch(void* const* d_in, const int* in_sizes, int n_in,
                              void* d_out, int out_size) {
    const float* inputs = (const float*)d_in[0];
    const float* labels = (const float*)d_in[1];
    float* out = (float*)d_out;

    rvsml_loss_kernel<<<NWORKERS, 256>>>(inputs, labels, out);
}

// round 9
// speedup vs baseline: 1.0506x; 1.0506x over previous
#include <cuda_runtime.h>
#include <cuda_bf16.h>

#define LGT      16
#define NROWS    4096
#define DCOLS    16000          // CLASSNUM * LGT
#define NWORKERS (152 * 8)      // GB300: 152 SMs, 8 CTAs/SM resident

__device__ float        g_acc  = 0.0f;
__device__ unsigned int g_cnt  = 0u;
__device__ unsigned int g_task = 0u;

__global__ __launch_bounds__(256, 8)
void rvsml_loss_kernel(const float* __restrict__ inputs,
                       const float* __restrict__ labels,
                       float* __restrict__ out) {
    const int tid  = threadIdx.x;
    const int wid  = tid >> 5;
    const int lane = tid & 31;

    __shared__ float    warp_sums[8];
    __shared__ unsigned next_sh[2];   // parity double-buffered ticket

    // Prologue: first ticket
    if (tid == 0) next_sh[0] = atomicAdd(&g_task, 1u);
    __syncthreads();
    unsigned row = next_sh[0];

    float total = 0.0f;   // per-thread running contribution
    int   k     = 0;      // iteration parity

    while (row < NROWS) {
        // Prefetch next ticket into the other parity slot; ATOMG latency
        // (~320cyc) hides under the row stream below. Slot (k+1)&1 was
        // last read before the previous barrier.
        if (tid == 0) next_sh[(k + 1) & 1] = atomicAdd(&g_task, 1u);

        // ---- Labels (per-warp broadcast loads; L1-hot, no block sync) ----
        const float* lab = labels + row * (LGT + 1);
        float lv = (lane <= LGT) ? __ldg(lab + lane) : 0.0f;
        const int   c = (int)__shfl_sync(0xFFFFFFFFu, lv, LGT);
        const float w = (lane < LGT) ? lv : 0.0f;
        float W = w;
        #pragma unroll
        for (int off = 16; off > 0; off >>= 1)
            W += __shfl_xor_sync(0xFFFFFFFFu, W, off);

        // ---- Stream the row, block-thread-strided (proven best layout) ----
        const float4* rowp =
            reinterpret_cast<const float4*>(inputs + (size_t)row * DCOLS);
        float sq = 0.0f;
        #pragma unroll 4
        for (int i = tid; i < DCOLS / 4; i += 256) {
            float4 v = rowp[i];
            sq = fmaf(v.x, v.x, sq);
            sq = fmaf(v.y, v.y, sq);
            sq = fmaf(v.z, v.z, sq);
            sq = fmaf(v.w, v.w, sq);
        }
        // Fold W_i * (this thread's partial sq) -- linearity means no
        // per-row reduction is needed at all.
        total = fmaf(W, sq, total);

        // ---- Gather term, once per row (warp 0 lanes 0..15) ----
        if (wid == 0 && lane < LGT) {
            const float g = __ldg(inputs + (size_t)row * DCOLS + c * LGT + lane);
            total = fmaf(w, 1.0f - 2.0f * g, total);
        }

        // ---- Single barrier per row: publish next ticket ----
        __syncthreads();
        row = next_sh[(k + 1) & 1];
        k++;
    }

    // ---- One block reduce + one global atomic per CTA (epilogue) ----
    #pragma unroll
    for (int off = 16; off > 0; off >>= 1)
        total += __shfl_xor_sync(0xFFFFFFFFu, total, off);
    if (lane == 0) warp_sums[wid] = total;
    __syncthreads();

    if (tid < 32) {
        float v = (tid < 8) ? warp_sums[tid] : 0.0f;
        #pragma unroll
        for (int off = 4; off > 0; off >>= 1)
            v += __shfl_xor_sync(0xFFFFFFFFu, v, off);

        if (tid == 0) {
            atomicAdd(&g_acc, v);
            __threadfence();
            const unsigned done = atomicAdd(&g_cnt, 1u);
            if (done == NWORKERS - 1) {
                // All contributions visible (each CTA fenced before its
                // counter increment). Read + reset for the next graph replay.
                const float t = atomicExch(&g_acc, 0.0f);
                out[0] = t * (1.0f / (float)NROWS);
                g_cnt  = 0u;
                g_task = 0u;
                __threadfence();
            }
        }
    }
}

extern "C" void kernel_launch(void* const* d_in, const int* in_sizes, int n_in,
                              void* d_out, int out_size) {
    const float* inputs = (const float*)d_in[0];
    const float* labels = (const float*)d_in[1];
    float* out = (float*)d_out;

    rvsml_loss_kernel<<<NWORKERS, 256>>>(inputs, labels, out);
}